// round 17
// baseline (speedup 1.0000x reference)
#include <cuda_runtime.h>
#include <cuda_fp16.h>
#include <math.h>

#define NN 8192
#define DD 256
#define HH 64

// Pre-scaled features: he[j, d] = e_j * h[j, d], fp16 (4 MB, L2-resident).
__device__ __half g_he[NN * DD];

// Packed fp32x2 helpers (sm_103a FFMA2 — ptxas never auto-fuses; PTX only).
#define SPLAT_F32X2(out, f) \
  asm("mov.b64 %0, {%1, %1};" : "=l"(out) : "r"(__float_as_uint(f)))
#define PACK_F32X2P(out, lo, hi) \
  asm("mov.b64 %0, {%1, %2};" : "=l"(out) \
      : "r"(__float_as_uint(lo)), "r"(__float_as_uint(hi)))
#define FMA_F32X2(d, a, b, c) \
  asm("fma.rn.f32x2 %0, %1, %2, %3;" : "=l"(d) : "l"(a), "l"(b), "l"(c))

__device__ __forceinline__ float f32x2_lo(unsigned long long v) {
  return __uint_as_float((unsigned)(v & 0xffffffffull));
}
__device__ __forceinline__ float f32x2_hi(unsigned long long v) {
  return __uint_as_float((unsigned)(v >> 32));
}

// ---------------------------------------------------------------------------
// Kernel 1: e = sigmoid(relu(h @ W1 + b1) @ W2 + b2); emit he = e*h (fp16).
// R15 shape (2-way k-split, 16 rows/block, 512 blocks, 128 threads) with the
// inner loop in PACKED fp32x2: per k4 per row = 4 splats + 8 fma2
// (fma-pipe 64 cyc/warp/k4 vs 128 for scalar FFMA). W1 j-pairs are the
// natural 64-bit halves of each float4 row (ulonglong2 LDG.128).
// ---------------------------------------------------------------------------
#define MLP_ROWS 16
__global__ void __launch_bounds__(128) mlp_kernel(
    const float* __restrict__ h, const float* __restrict__ W1,
    const float* __restrict__ b1, const float* __restrict__ W2,
    const float* __restrict__ b2, float* __restrict__ out_e) {

  __shared__ __align__(16) float sh_h[MLP_ROWS * DD];       // 16 KB
  __shared__ __align__(16) float4 sAcc[MLP_ROWS][16];       // 4 KB partials
  __shared__ float sPart[MLP_ROWS][17];
  __shared__ float sE[MLP_ROWS];

  const int tid = threadIdx.x;
  const int kh = tid >> 6;                  // 0..1 -> k half
  const int rg = (tid >> 4) & 3;            // 0..3 -> rows rg*4 .. +3
  const int jg = tid & 15;                  // 0..15 -> j jg*4 .. +3
  const int j0 = jg * 4;
  const int rowbase = blockIdx.x * MLP_ROWS;

  // Stage 16 h rows (1024 float4 / 128 thr = 8 each), coalesced.
  {
    const float4* src = (const float4*)(h + (size_t)rowbase * DD);
    float4* dst = (float4*)sh_h;
    #pragma unroll
    for (int i = tid; i < MLP_ROWS * DD / 4; i += 128) dst[i] = __ldg(&src[i]);
  }
  __syncthreads();

  // Packed accumulators: acc2[a][0] = (j0,j1), acc2[a][1] = (j2,j3).
  unsigned long long acc2[4][2];
  if (kh == 0) {
    const float4 b = __ldg((const float4*)(b1 + j0));
    unsigned long long b01, b23;
    PACK_F32X2P(b01, b.x, b.y);
    PACK_F32X2P(b23, b.z, b.w);
    #pragma unroll
    for (int a = 0; a < 4; a++) { acc2[a][0] = b01; acc2[a][1] = b23; }
  } else {
    #pragma unroll
    for (int a = 0; a < 4; a++) { acc2[a][0] = 0ull; acc2[a][1] = 0ull; }
  }

  const float4* sh4 = (const float4*)sh_h;
  const ulonglong2* W1p = (const ulonglong2*)W1;  // row k: 16 u2 = 64 floats;
                                                  // u2.x=(j0,j1), u2.y=(j2,j3)

  #pragma unroll 4
  for (int k4 = 0; k4 < 32; k4++) {
    const int kg = kh * 32 + k4;
    float4 hv[4];
    #pragma unroll
    for (int a = 0; a < 4; a++)
      hv[a] = sh4[(rg * 4 + a) * (DD / 4) + kg];          // broadcast LDS.128

    const ulonglong2 wA = __ldg(&W1p[(kg * 4 + 0) * 16 + jg]);
    const ulonglong2 wB = __ldg(&W1p[(kg * 4 + 1) * 16 + jg]);
    const ulonglong2 wC = __ldg(&W1p[(kg * 4 + 2) * 16 + jg]);
    const ulonglong2 wD = __ldg(&W1p[(kg * 4 + 3) * 16 + jg]);

    #pragma unroll
    for (int a = 0; a < 4; a++) {
      unsigned long long s;
      SPLAT_F32X2(s, hv[a].x);
      FMA_F32X2(acc2[a][0], s, wA.x, acc2[a][0]);
      FMA_F32X2(acc2[a][1], s, wA.y, acc2[a][1]);
      SPLAT_F32X2(s, hv[a].y);
      FMA_F32X2(acc2[a][0], s, wB.x, acc2[a][0]);
      FMA_F32X2(acc2[a][1], s, wB.y, acc2[a][1]);
      SPLAT_F32X2(s, hv[a].z);
      FMA_F32X2(acc2[a][0], s, wC.x, acc2[a][0]);
      FMA_F32X2(acc2[a][1], s, wC.y, acc2[a][1]);
      SPLAT_F32X2(s, hv[a].w);
      FMA_F32X2(acc2[a][0], s, wD.x, acc2[a][0]);
      FMA_F32X2(acc2[a][1], s, wD.y, acc2[a][1]);
    }
  }

  // Publish kh=1 partials (unpacked); kh=0 combines, relu, W2 dot.
  if (kh == 1) {
    #pragma unroll
    for (int a = 0; a < 4; a++)
      sAcc[rg * 4 + a][jg] =
          make_float4(f32x2_lo(acc2[a][0]), f32x2_hi(acc2[a][0]),
                      f32x2_lo(acc2[a][1]), f32x2_hi(acc2[a][1]));
  }
  __syncthreads();

  if (kh == 0) {
    const float4 w2 = __ldg((const float4*)(W2 + j0));
    #pragma unroll
    for (int a = 0; a < 4; a++) {
      const float4 o = sAcc[rg * 4 + a][jg];
      const float t0 = f32x2_lo(acc2[a][0]) + o.x;
      const float t1 = f32x2_hi(acc2[a][0]) + o.y;
      const float t2 = f32x2_lo(acc2[a][1]) + o.z;
      const float t3 = f32x2_hi(acc2[a][1]) + o.w;
      sPart[rg * 4 + a][jg] =
          fmaxf(t0, 0.0f) * w2.x + fmaxf(t1, 0.0f) * w2.y +
          fmaxf(t2, 0.0f) * w2.z + fmaxf(t3, 0.0f) * w2.w;
    }
  }
  __syncthreads();

  if (tid < MLP_ROWS) {
    float s = __ldg(&b2[0]);
    #pragma unroll
    for (int g = 0; g < 16; g++) s += sPart[tid][g];
    const float ev = 1.0f / (1.0f + expf(-s));
    sE[tid] = ev;
    out_e[rowbase + tid] = ev;
  }
  __syncthreads();

  // Emit he16 = e_row * h from smem (8 float4 per thread).
  __half2* he2 = (__half2*)g_he;
  #pragma unroll
  for (int i = tid; i < MLP_ROWS * (DD / 4); i += 128) {
    const int r = i >> 6;
    const float4 hv = ((const float4*)sh_h)[i];
    const float e = sE[r];
    const size_t base = ((size_t)rowbase * DD + i * 4) >> 1;
    he2[base]     = __floats2half2_rn(hv.x * e, hv.y * e);
    he2[base + 1] = __floats2half2_rn(hv.z * e, hv.w * e);
  }
}

// ---------------------------------------------------------------------------
// Kernel 2 (FROZEN R10 agg — 50.75-52.7 us over 6 runs, LTS/DRAM bound):
// h_out[i,:] = sum_{j: A[i,j] > 0} he[j,:]
// One block (8 warps) per row; each warp independent on its 1/8 slice:
//   scan: 8 front-batched __ldcs uint4 -> 32-bit register pending mask
//   gather: per round, 1 ballot picks up to 4 source lanes; shfl their j's;
//           4 independent warp-LDG.128 of fp16 he rows; owners clear a bit.
// Single __syncthreads per row (cross-warp reduce).
// ---------------------------------------------------------------------------
__global__ void __launch_bounds__(256) agg_kernel(const float* __restrict__ A,
                                                  float* __restrict__ out) {
  __shared__ __align__(16) float s_red[8][DD];   // 8 KB

  const int row = blockIdx.x;
  const int tid = threadIdx.x;
  const int wid = tid >> 5;
  const int lane = tid & 31;

  const uint4* Aslice = (const uint4*)(A + (size_t)row * NN) + wid * 256;

  uint4 av[8];
  #pragma unroll
  for (int r = 0; r < 8; r++)
    av[r] = __ldcs(Aslice + r * 32 + lane);

  unsigned pending = 0u;
  #pragma unroll
  for (int r = 0; r < 8; r++) {
    unsigned f = 0u;
    if (av[r].x) f |= 1u;
    if (av[r].y) f |= 2u;
    if (av[r].z) f |= 4u;
    if (av[r].w) f |= 8u;
    pending |= f << (r * 4);
  }

  const uint4* he4 = (const uint4*)g_he;
  float acc[8] = {0.f, 0.f, 0.f, 0.f, 0.f, 0.f, 0.f, 0.f};

  while (true) {
    unsigned m = __ballot_sync(0xFFFFFFFFu, pending != 0u);
    if (!m) break;

    const int b = __ffs(pending) - 1;
    const int jmine = wid * 1024 + ((b & ~3) << 5) + (lane << 2) + (b & 3);

    const int n = __popc(m) < 4 ? __popc(m) : 4;
    int s0 = __ffs(m) - 1;            m &= m - 1;
    int s1 = m ? __ffs(m) - 1 : s0;   m &= m - 1;
    int s2 = m ? __ffs(m) - 1 : s0;   m &= m - 1;
    int s3 = m ? __ffs(m) - 1 : s0;

    const int j0 = __shfl_sync(0xFFFFFFFFu, jmine, s0);
    const int j1 = __shfl_sync(0xFFFFFFFFu, jmine, s1);
    const int j2 = __shfl_sync(0xFFFFFFFFu, jmine, s2);
    const int j3 = __shfl_sync(0xFFFFFFFFu, jmine, s3);

    if (lane == s0 || (n > 1 && lane == s1) || (n > 2 && lane == s2) ||
        (n > 3 && lane == s3))
      pending &= pending - 1u;

    uint4 v0, v1, v2, v3;
    v0 = __ldg(&he4[(size_t)j0 * 32 + lane]);
    if (n > 1) v1 = __ldg(&he4[(size_t)j1 * 32 + lane]);
    if (n > 2) v2 = __ldg(&he4[(size_t)j2 * 32 + lane]);
    if (n > 3) v3 = __ldg(&he4[(size_t)j3 * 32 + lane]);

    {
      const __half2* p = (const __half2*)&v0;
      #pragma unroll
      for (int q = 0; q < 4; q++) {
        const float2 f = __half22float2(p[q]);
        acc[2 * q] += f.x; acc[2 * q + 1] += f.y;
      }
    }
    if (n > 1) {
      const __half2* p = (const __half2*)&v1;
      #pragma unroll
      for (int q = 0; q < 4; q++) {
        const float2 f = __half22float2(p[q]);
        acc[2 * q] += f.x; acc[2 * q + 1] += f.y;
      }
    }
    if (n > 2) {
      const __half2* p = (const __half2*)&v2;
      #pragma unroll
      for (int q = 0; q < 4; q++) {
        const float2 f = __half22float2(p[q]);
        acc[2 * q] += f.x; acc[2 * q + 1] += f.y;
      }
    }
    if (n > 3) {
      const __half2* p = (const __half2*)&v3;
      #pragma unroll
      for (int q = 0; q < 4; q++) {
        const float2 f = __half22float2(p[q]);
        acc[2 * q] += f.x; acc[2 * q + 1] += f.y;
      }
    }
  }

  {
    float4* rr = (float4*)s_red[wid];
    rr[lane * 2]     = make_float4(acc[0], acc[1], acc[2], acc[3]);
    rr[lane * 2 + 1] = make_float4(acc[4], acc[5], acc[6], acc[7]);
  }
  __syncthreads();

  float s = 0.0f;
  #pragma unroll
  for (int w = 0; w < 8; w++) s += s_red[w][tid];
  out[(size_t)row * DD + tid] = s;
}

// ---------------------------------------------------------------------------
// Inputs (setup_inputs order):
//   0: graph_info [N*N], 1: h [N*D], 2: W1 [D*H], 3: b1 [H], 4: W2 [H], 5: b2 [1]
// Output: h_out [N*D] followed by e [N].
// ---------------------------------------------------------------------------
extern "C" void kernel_launch(void* const* d_in, const int* in_sizes, int n_in,
                              void* d_out, int out_size) {
  const float* A  = (const float*)d_in[0];
  const float* h  = (const float*)d_in[1];
  const float* W1 = (const float*)d_in[2];
  const float* b1 = (const float*)d_in[3];
  const float* W2 = (const float*)d_in[4];
  const float* b2 = (const float*)d_in[5];

  float* out_h = (float*)d_out;                     // [N*D]
  float* out_e = (float*)d_out + (size_t)NN * DD;   // [N]

  mlp_kernel<<<NN / MLP_ROWS, 128>>>(h, W1, b1, W2, b2, out_e);
  agg_kernel<<<NN, 256>>>(A, out_h);
}